// round 2
// baseline (speedup 1.0000x reference)
#include <cuda_runtime.h>

// Problem constants
#define HW 4096            // 64*64
#define CIN 128
#define NOFF 18            // 2*K2
#define KD 1152            // CIN*9

// Scratch (device globals; no allocation allowed)
__device__ float g_h[8 * 128 * HW];        // BN+ReLU output, 16 MB
__device__ float g_off1[8 * NOFF * HW];    // conv_offsets
__device__ float g_off2[8 * NOFF * HW];    // dconv_offsets
__device__ float g_wt[KD * 128];           // dc_w transposed: [c*9+k2][oc]

// ---------------------------------------------------------------------------
// K1: BN + ReLU (vectorized float4). n = 8*128*4096 floats = 1048576 float4.
// ---------------------------------------------------------------------------
__global__ void k_bnrelu(const float* __restrict__ x,
                         const float* __restrict__ gamma,
                         const float* __restrict__ beta,
                         const float* __restrict__ mean,
                         const float* __restrict__ var) {
    int i = blockIdx.x * blockDim.x + threadIdx.x;   // float4 index
    int c = (i >> 10) & 127;                         // 1024 float4 per channel
    float s = rsqrtf(var[c] + 1e-5f) * gamma[c];
    float m = mean[c], bt = beta[c];
    float4 v = ((const float4*)x)[i];
    v.x = fmaxf((v.x - m) * s + bt, 0.f);
    v.y = fmaxf((v.y - m) * s + bt, 0.f);
    v.z = fmaxf((v.z - m) * s + bt, 0.f);
    v.w = fmaxf((v.w - m) * s + bt, 0.f);
    ((float4*)g_h)[i] = v;
}

// ---------------------------------------------------------------------------
// K0: transpose dc_w [oc][c*9+k2] -> g_wt [c*9+k2][oc]. 147456 elements.
// ---------------------------------------------------------------------------
__global__ void k_transpose_w(const float* __restrict__ w) {
    int i = blockIdx.x * blockDim.x + threadIdx.x;
    int oc = i & 127, j = i >> 7;
    g_wt[i] = w[oc * KD + j];
}

// ---------------------------------------------------------------------------
// K2: 3x3 conv, 18 output channels (offset-predicting conv).
// 128 threads = 2 rows; each thread one pixel, 18 accumulators.
// Weights staged in smem in 32-channel chunks. Writes g_off1 directly.
// ---------------------------------------------------------------------------
__global__ void k_conv18(const float* __restrict__ wq,
                         const float* __restrict__ bias) {
    __shared__ float ws[NOFF * 288];   // [oc][c_local*9+k], 20.7 KB
    int tid = threadIdx.x;
    int row = blockIdx.x * 2 + (tid >> 6);   // b*64+y
    int b = row >> 6, y = row & 63, x = tid & 63;

    float acc[NOFF];
#pragma unroll
    for (int o = 0; o < NOFF; o++) acc[o] = bias[o];

    for (int c0 = 0; c0 < CIN; c0 += 32) {
        __syncthreads();
        for (int i = tid; i < NOFF * 288; i += 128) {
            int oc = i / 288, r = i - oc * 288;
            ws[i] = wq[oc * KD + c0 * 9 + r];
        }
        __syncthreads();
        for (int cl = 0; cl < 32; cl++) {
            const float* hp = g_h + ((b << 7) + (c0 + cl)) * HW;
            float v[9];
#pragma unroll
            for (int ky = 0; ky < 3; ky++) {
                int yy = y + ky - 1;
                bool vy = ((unsigned)yy < 64u);
                int rb = yy * 64 + x;
                v[ky * 3 + 0] = (vy && x > 0)  ? hp[rb - 1] : 0.f;
                v[ky * 3 + 1] = vy             ? hp[rb]     : 0.f;
                v[ky * 3 + 2] = (vy && x < 63) ? hp[rb + 1] : 0.f;
            }
#pragma unroll
            for (int o = 0; o < NOFF; o++) {
                const float* wr = ws + o * 288 + cl * 9;
#pragma unroll
                for (int k = 0; k < 9; k++) acc[o] = fmaf(v[k], wr[k], acc[o]);
            }
        }
    }
    int base = b * NOFF * HW + y * 64 + x;
#pragma unroll
    for (int o = 0; o < NOFF; o++) g_off1[base + o * HW] = acc[o];
}

// ---------------------------------------------------------------------------
// K3: deformable conv, 18 output channels. Same thread layout as K2.
// Bilinear params recomputed per (chunk, tap); 4 gathers per (tap, channel).
// ---------------------------------------------------------------------------
__global__ void k_dconv18(const float* __restrict__ wq,
                          const float* __restrict__ bias) {
    __shared__ float ws[NOFF * 288];
    int tid = threadIdx.x;
    int row = blockIdx.x * 2 + (tid >> 6);
    int b = row >> 6, y = row & 63, x = tid & 63;

    float acc[NOFF];
#pragma unroll
    for (int o = 0; o < NOFF; o++) acc[o] = bias[o];

    const float* offp = g_off1 + b * NOFF * HW + y * 64 + x;

    for (int c0 = 0; c0 < CIN; c0 += 32) {
        __syncthreads();
        for (int i = tid; i < NOFF * 288; i += 128) {
            int oc = i / 288, r = i - oc * 288;
            ws[i] = wq[oc * KD + c0 * 9 + r];
        }
        __syncthreads();
        for (int k2 = 0; k2 < 9; k2++) {
            float dy = offp[(2 * k2) * HW];
            float dx = offp[(2 * k2 + 1) * HW];
            float py = (float)(y - 1 + k2 / 3) + dy;
            float px = (float)(x - 1 + k2 % 3) + dx;
            float fy0 = floorf(py), fx0 = floorf(px);
            float wy1 = py - fy0, wx1 = px - fx0;
            float wy0 = 1.f - wy1, wx0 = 1.f - wx1;
            int iy0 = (int)fy0, ix0 = (int)fx0;
            int iy1 = iy0 + 1, ix1 = ix0 + 1;
            bool vy0 = ((unsigned)iy0 < 64u), vy1 = ((unsigned)iy1 < 64u);
            bool vx0 = ((unsigned)ix0 < 64u), vx1 = ((unsigned)ix1 < 64u);
            float w00 = (vy0 && vx0) ? wy0 * wx0 : 0.f;
            float w01 = (vy0 && vx1) ? wy0 * wx1 : 0.f;
            float w10 = (vy1 && vx0) ? wy1 * wx0 : 0.f;
            float w11 = (vy1 && vx1) ? wy1 * wx1 : 0.f;
            int cy0 = min(max(iy0, 0), 63), cy1 = min(max(iy1, 0), 63);
            int cx0 = min(max(ix0, 0), 63), cx1 = min(max(ix1, 0), 63);
            int i00 = cy0 * 64 + cx0, i01 = cy0 * 64 + cx1;
            int i10 = cy1 * 64 + cx0, i11 = cy1 * 64 + cx1;

            const float* hp = g_h + ((b << 7) + c0) * HW;
            for (int cl = 0; cl < 32; cl++, hp += HW) {
                float s = w00 * hp[i00] + w01 * hp[i01]
                        + w10 * hp[i10] + w11 * hp[i11];
#pragma unroll
                for (int o = 0; o < NOFF; o++)
                    acc[o] = fmaf(s, ws[o * 288 + cl * 9 + k2], acc[o]);
            }
        }
    }
    int base = b * NOFF * HW + y * 64 + x;
#pragma unroll
    for (int o = 0; o < NOFF; o++) g_off2[base + o * HW] = acc[o];
}

// ---------------------------------------------------------------------------
// K4: deformable conv, 128 output channels — GEMM-tiled.
// Block: 32 pixels (half row) x 128 oc, 256 threads, 4x4 register tile.
// A-tile: sampled im2col [36][32] per 4-channel chunk; B-tile from g_wt.
// ---------------------------------------------------------------------------
__global__ void __launch_bounds__(256) k_dconv128(
        const float* __restrict__ bias, float* __restrict__ out) {
    __shared__ float s_w[4][288];    // bilinear weights [corner][k2*32+pix]
    __shared__ int   s_idx[4][288];  // clamped flat index y*64+x
    __shared__ float s_a[36][32];    // sampled A tile (j = c_local*9+k2)
    __shared__ float s_b[36 * 128];  // weight B tile

    int tid = threadIdx.x;
    int blk = blockIdx.x;            // 1024 blocks
    int xh = blk & 1, row = blk >> 1;
    int b = row >> 6, y = row & 63, x0 = xh * 32;

    // Phase 0: bilinear setup for 32 pixels x 9 taps (288 pairs)
    for (int t = tid; t < 288; t += 256) {
        int pix = t & 31, k2 = t >> 5;
        int x = x0 + pix;
        const float* offp = g_off2 + b * NOFF * HW + y * 64 + x;
        float dy = offp[(2 * k2) * HW];
        float dx = offp[(2 * k2 + 1) * HW];
        float py = (float)(y - 1 + k2 / 3) + dy;
        float px = (float)(x - 1 + k2 % 3) + dx;
        float fy0 = floorf(py), fx0 = floorf(px);
        float wy1 = py - fy0, wx1 = px - fx0;
        float wy0 = 1.f - wy1, wx0 = 1.f - wx1;
        int iy0 = (int)fy0, ix0 = (int)fx0;
        int iy1 = iy0 + 1, ix1 = ix0 + 1;
        bool vy0 = ((unsigned)iy0 < 64u), vy1 = ((unsigned)iy1 < 64u);
        bool vx0 = ((unsigned)ix0 < 64u), vx1 = ((unsigned)ix1 < 64u);
        s_w[0][t] = (vy0 && vx0) ? wy0 * wx0 : 0.f;
        s_w[1][t] = (vy0 && vx1) ? wy0 * wx1 : 0.f;
        s_w[2][t] = (vy1 && vx0) ? wy1 * wx0 : 0.f;
        s_w[3][t] = (vy1 && vx1) ? wy1 * wx1 : 0.f;
        int cy0 = min(max(iy0, 0), 63), cy1 = min(max(iy1, 0), 63);
        int cx0 = min(max(ix0, 0), 63), cx1 = min(max(ix1, 0), 63);
        s_idx[0][t] = cy0 * 64 + cx0;
        s_idx[1][t] = cy0 * 64 + cx1;
        s_idx[2][t] = cy1 * 64 + cx0;
        s_idx[3][t] = cy1 * 64 + cx1;
    }

    float acc[4][4];
#pragma unroll
    for (int i = 0; i < 4; i++)
#pragma unroll
        for (int j = 0; j < 4; j++) acc[i][j] = 0.f;

    __syncthreads();

    const float* hb = g_h + (b << 7) * HW;
    int pq = tid & 7, oq = tid >> 3;     // pixel quad, oc quad

    for (int cc = 0; cc < 32; cc++) {    // 4-channel chunks
        // Fill A tile: 36 x 32 sampled values
        for (int ii = tid; ii < 1152; ii += 256) {
            int pix = ii & 31, j = ii >> 5;
            int cl = j / 9, k2 = j - cl * 9;
            int pt = k2 * 32 + pix;
            const float* hp = hb + (cc * 4 + cl) * HW;
            float v = s_w[0][pt] * hp[s_idx[0][pt]]
                    + s_w[1][pt] * hp[s_idx[1][pt]]
                    + s_w[2][pt] * hp[s_idx[2][pt]]
                    + s_w[3][pt] * hp[s_idx[3][pt]];
            s_a[j][pix] = v;
        }
        // Fill B tile: 36 x 128 weights (contiguous in g_wt)
        const float4* wsrc = (const float4*)g_wt + cc * 1152;
        for (int ii = tid; ii < 1152; ii += 256)
            ((float4*)s_b)[ii] = wsrc[ii];
        __syncthreads();

#pragma unroll
        for (int j = 0; j < 36; j++) {
            float4 a = *(const float4*)&s_a[j][pq * 4];
            float4 w = *(const float4*)&s_b[j * 128 + oq * 4];
            acc[0][0] += a.x * w.x; acc[0][1] += a.y * w.x;
            acc[0][2] += a.z * w.x; acc[0][3] += a.w * w.x;
            acc[1][0] += a.x * w.y; acc[1][1] += a.y * w.y;
            acc[1][2] += a.z * w.y; acc[1][3] += a.w * w.y;
            acc[2][0] += a.x * w.z; acc[2][1] += a.y * w.z;
            acc[2][2] += a.z * w.z; acc[2][3] += a.w * w.z;
            acc[3][0] += a.x * w.w; acc[3][1] += a.y * w.w;
            acc[3][2] += a.z * w.w; acc[3][3] += a.w * w.w;
        }
        __syncthreads();
    }

    // Epilogue: bias + float4 stores
#pragma unroll
    for (int oi = 0; oi < 4; oi++) {
        int oc = oq * 4 + oi;
        float bs = bias[oc];
        float4 r;
        r.x = acc[oi][0] + bs;
        r.y = acc[oi][1] + bs;
        r.z = acc[oi][2] + bs;
        r.w = acc[oi][3] + bs;
        *(float4*)&out[((b << 7) + oc) * HW + y * 64 + x0 + pq * 4] = r;
    }
}

// ---------------------------------------------------------------------------
// Launch. Input order (metadata): x, bn_gamma, bn_beta, bn_mean, bn_var,
// off_w, off_b, odc_w, odc_b, dc_w, dc_b. Output: float32 [8,128,64,64].
// ---------------------------------------------------------------------------
extern "C" void kernel_launch(void* const* d_in, const int* in_sizes, int n_in,
                              void* d_out, int out_size) {
    const float* x     = (const float*)d_in[0];
    const float* gamma = (const float*)d_in[1];
    const float* beta  = (const float*)d_in[2];
    const float* mean  = (const float*)d_in[3];
    const float* var   = (const float*)d_in[4];
    const float* off_w = (const float*)d_in[5];
    const float* off_b = (const float*)d_in[6];
    const float* odc_w = (const float*)d_in[7];
    const float* odc_b = (const float*)d_in[8];
    const float* dc_w  = (const float*)d_in[9];
    const float* dc_b  = (const float*)d_in[10];
    float* out = (float*)d_out;

    k_bnrelu<<<4096, 256>>>(x, gamma, beta, mean, var);
    k_transpose_w<<<576, 256>>>(dc_w);
    k_conv18<<<256, 128>>>(off_w, off_b);
    k_dconv18<<<256, 128>>>(odc_w, odc_b);
    k_dconv128<<<1024, 256>>>(dc_b, out);
}